// round 15
// baseline (speedup 1.0000x reference)
#include <cuda_runtime.h>
#include <cstdint>
#include <math.h>

#define BB 4
#define TT 2048
#define CC 1024
#define HH 2048

// ---- scratch (device globals; allocation-free rule) -----------------------
__device__ float g_q[(size_t)BB * TT * HH];
__device__ float g_k[(size_t)BB * TT * HH];
__device__ float g_v[(size_t)BB * TT * HH];      // V TRANSPOSED: [B][H][T]
__device__ float g_s[(size_t)BB * TT * TT];
__device__ float g_xr[(size_t)BB * TT * CC];     // tf32-rounded x
__device__ float g_wr[(size_t)3 * HH * CC];      // tf32-rounded Wk|Wq|Wv

// ---- helpers --------------------------------------------------------------
__device__ __forceinline__ uint32_t smem_u32(const void* p) {
    uint32_t a;
    asm("{ .reg .u64 t; cvta.to.shared.u64 t, %1; cvt.u32.u64 %0, t; }"
        : "=r"(a) : "l"(p));
    return a;
}
__device__ __forceinline__ float tf32r(float v) {
    uint32_t u;
    asm("cvt.rna.tf32.f32 %0, %1;" : "=r"(u) : "f"(v));
    return __uint_as_float(u);
}

#define CP16(dst, src) \
    asm volatile("cp.async.cg.shared.global [%0], [%1], 16;" \
                 :: "r"(dst), "l"(src))
#define CP_COMMIT() asm volatile("cp.async.commit_group;" ::: "memory")
#define CP_WAIT1()  asm volatile("cp.async.wait_group 1;" ::: "memory")
#define CP_WAIT0()  asm volatile("cp.async.wait_group 0;" ::: "memory")

#define LDSM4(r0, r1, r2, r3, a) \
    asm volatile("ldmatrix.sync.aligned.m8n8.x4.shared.b16 {%0,%1,%2,%3}, [%4];" \
                 : "=r"(r0), "=r"(r1), "=r"(r2), "=r"(r3) : "r"(a))

#define MMA8(d, a, b0, b1) \
    asm volatile("mma.sync.aligned.m16n8k8.row.col.f32.tf32.tf32.f32 " \
        "{%0,%1,%2,%3}, {%4,%5,%6,%7}, {%8,%9}, {%0,%1,%2,%3};" \
        : "+f"((d)[0]), "+f"((d)[1]), "+f"((d)[2]), "+f"((d)[3]) \
        : "r"((a)[0]), "r"((a)[1]), "r"((a)[2]), "r"((a)[3]), \
          "r"(b0), "r"(b1))

// ---- GEMM config ----------------------------------------------------------
#define BM 128
#define BN 256
#define BK 32
#define PADK 36                          // floats per smem row (144B; 9x16B)
#define TBUFA (BM * PADK)                // 4608 floats
#define TBUFB (BN * PADK)                // 9216 floats
#define TBUFA_B (TBUFA * 4)              // 18432 B
#define TBUFB_B (TBUFB * 4)              // 36864 B
#define SMEM_BYTES (2 * TBUFA_B + 2 * TBUFB_B)   // 110592 B

// ---------------------------------------------------------------------------
// C[M,N] = scale * A[M,K] * B[N,K]^T  (row-major, K contiguous)
// tf32 mma.sync m16n8k8, 128x256x32 tiles, 8 warps (2x4), warp tile 64x64,
// cp.async double buffer, all-x4 ldmatrix.
// causal: skip tiles 2*bx > by (BN=2*BM).  klimit: K bounded at (by+1)*BM.
// round_out: RNA-round outputs to tf32 (tensors feeding another MMA).
// ---------------------------------------------------------------------------
__global__ __launch_bounds__(256, 1)
void mma_nt(const float* __restrict__ A, const float* __restrict__ B,
            float* __restrict__ C, int M, int N, int K, float scale,
            int causal, int klimit, int round_out,
            long long sA, long long sB, long long sC)
{
    int bx = blockIdx.x, by = blockIdx.y, bz = blockIdx.z;
    if (causal && 2 * bx > by) return;
    A += (long long)bz * sA;
    B += (long long)bz * sB;
    C += (long long)bz * sC;

    extern __shared__ float dsm[];
    float* As = dsm;                     // [2][TBUFA]
    float* Bs = dsm + 2 * TBUFA;         // [2][TBUFB]

    int tid = threadIdx.x;
    int lane = tid & 31, wid = tid >> 5;
    int warp_m = wid >> 2;               // 0..1 -> 64-row half
    int warp_n = wid & 3;                // 0..3 -> 64-col quarter

    const float* Ab = A + (size_t)(by * BM) * K;
    const float* Bb = B + (size_t)(bx * BN) * K;

    int kend = klimit ? min(K, (by + 1) * BM) : K;
    int nt = kend / BK;

    uint32_t as0 = smem_u32(As);
    uint32_t bs0 = smem_u32(Bs);

    // cp.async: rows of 32 floats = 8 16B chunks.
    // A: 128 rows -> 4 chunks/thread.  B: 256 rows -> 8 chunks/thread.
    int crow = tid >> 3;                 // 0..31 (+32*i)
    int ccol = (tid & 7) * 4;            // float offset in row
    uint32_t dA = as0 + (uint32_t)(crow * PADK + ccol) * 4;
    uint32_t dB = bs0 + (uint32_t)(crow * PADK + ccol) * 4;
    const float* sAp = Ab + (size_t)crow * K + ccol;
    const float* sBp = Bb + (size_t)crow * K + ccol;
    const uint32_t rstep = 32 * PADK * 4;    // 32 rows in smem bytes

    // ldmatrix bases
    uint32_t aAddr = as0 + (uint32_t)(((warp_m * 64 + (lane & 15)) * PADK
                                       + (lane >> 4) * 4) * 4);
    uint32_t bAddr = bs0 + (uint32_t)(((warp_n * 64 + (lane & 7)
                                        + ((lane >> 4) & 1) * 8) * PADK
                                       + ((lane >> 3) & 1) * 4) * 4);

    float acc[4][8][4];
#pragma unroll
    for (int i = 0; i < 4; i++)
#pragma unroll
        for (int j = 0; j < 8; j++)
#pragma unroll
            for (int r = 0; r < 4; r++) acc[i][j][r] = 0.f;

    // preload tile 0
#pragma unroll
    for (int i = 0; i < 4; i++)
        CP16(dA + i * rstep, sAp + (size_t)(i * 32) * K);
#pragma unroll
    for (int i = 0; i < 8; i++)
        CP16(dB + i * rstep, sBp + (size_t)(i * 32) * K);
    CP_COMMIT();

    for (int t = 0; t < nt; t++) {
        uint32_t aoff = (uint32_t)(t & 1) * TBUFA_B;
        uint32_t boff = (uint32_t)(t & 1) * TBUFB_B;
        if (t + 1 < nt) {
            uint32_t naoff = (uint32_t)((t + 1) & 1) * TBUFA_B;
            uint32_t nboff = (uint32_t)((t + 1) & 1) * TBUFB_B;
            size_t ko = (size_t)(t + 1) * BK;
#pragma unroll
            for (int i = 0; i < 4; i++)
                CP16(dA + naoff + i * rstep, sAp + (size_t)(i * 32) * K + ko);
#pragma unroll
            for (int i = 0; i < 8; i++)
                CP16(dB + nboff + i * rstep, sBp + (size_t)(i * 32) * K + ko);
            CP_COMMIT();
            CP_WAIT1();
        } else {
            CP_WAIT0();
        }
        __syncthreads();

#pragma unroll
        for (int ks = 0; ks < 4; ks++) {
            uint32_t a[4][4], b[4][4];
#pragma unroll
            for (int mi = 0; mi < 4; mi++)
                LDSM4(a[mi][0], a[mi][1], a[mi][2], a[mi][3],
                      aAddr + aoff + (uint32_t)(mi * 16 * PADK * 4 + ks * 32));
#pragma unroll
            for (int g = 0; g < 4; g++)
                LDSM4(b[g][0], b[g][1], b[g][2], b[g][3],
                      bAddr + boff + (uint32_t)(g * 16 * PADK * 4 + ks * 32));
#pragma unroll
            for (int mi = 0; mi < 4; mi++)
#pragma unroll
                for (int g = 0; g < 4; g++) {
                    MMA8(acc[mi][2 * g],     a[mi], b[g][0], b[g][1]);
                    MMA8(acc[mi][2 * g + 1], a[mi], b[g][2], b[g][3]);
                }
        }
        __syncthreads();
    }

    // epilogue
#pragma unroll
    for (int mi = 0; mi < 4; mi++) {
#pragma unroll
        for (int ni = 0; ni < 8; ni++) {
            int r0 = by * BM + warp_m * 64 + mi * 16 + (lane >> 2);
            int c  = bx * BN + warp_n * 64 + ni * 8 + 2 * (lane & 3);
            float2 v0, v1;
            v0.x = acc[mi][ni][0] * scale; v0.y = acc[mi][ni][1] * scale;
            v1.x = acc[mi][ni][2] * scale; v1.y = acc[mi][ni][3] * scale;
            if (round_out) {
                v0.x = tf32r(v0.x); v0.y = tf32r(v0.y);
                v1.x = tf32r(v1.x); v1.y = tf32r(v1.y);
            }
            *(float2*)(C + (size_t)r0 * N + c)       = v0;
            *(float2*)(C + (size_t)(r0 + 8) * N + c) = v1;
        }
    }
}

// ---- tf32 pre-rounding pass ----------------------------------------------
__global__ __launch_bounds__(256)
void round_pass(const float* __restrict__ in, float* __restrict__ out, int n)
{
    int i = (blockIdx.x * 256 + threadIdx.x) * 4;
    if (i < n) {
        float4 v = *(const float4*)(in + i);
        v.x = tf32r(v.x); v.y = tf32r(v.y); v.z = tf32r(v.z); v.w = tf32r(v.w);
        *(float4*)(out + i) = v;
    }
}

// ---- causal softmax (in-place, float4), rounds P to tf32, zero diag tail --
__device__ __forceinline__ float warp_max(float v) {
#pragma unroll
    for (int o = 16; o; o >>= 1) v = fmaxf(v, __shfl_xor_sync(0xffffffffu, v, o));
    return v;
}
__device__ __forceinline__ float warp_sum(float v) {
#pragma unroll
    for (int o = 16; o; o >>= 1) v += __shfl_xor_sync(0xffffffffu, v, o);
    return v;
}

__global__ __launch_bounds__(256)
void softmax_causal(float* __restrict__ S, int T)
{
    int row = blockIdx.x;
    int b = row / T;
    int t = row - b * T;
    float* p = S + (long long)b * T * T + (long long)t * T;
    float4* p4 = (float4*)p;
    int n = t + 1;
    int n4 = n >> 2;

    int tid = threadIdx.x;
    int lane = tid & 31, wid = tid >> 5;
    __shared__ float red[8];

    float m = -INFINITY;
    for (int i = tid; i < n4; i += 256) {
        float4 v = p4[i];
        m = fmaxf(m, fmaxf(fmaxf(v.x, v.y), fmaxf(v.z, v.w)));
    }
    for (int i = n4 * 4 + tid; i < n; i += 256) m = fmaxf(m, p[i]);
    m = warp_max(m);
    if (lane == 0) red[wid] = m;
    __syncthreads();
    if (wid == 0) {
        float x = (lane < 8) ? red[lane] : -INFINITY;
        x = warp_max(x);
        if (lane == 0) red[0] = x;
    }
    __syncthreads();
    m = red[0];
    __syncthreads();

    float s = 0.f;
    for (int i = tid; i < n4; i += 256) {
        float4 v = p4[i];
        v.x = __expf(v.x - m); v.y = __expf(v.y - m);
        v.z = __expf(v.z - m); v.w = __expf(v.w - m);
        s += v.x + v.y + v.z + v.w;
        p4[i] = v;
    }
    for (int i = n4 * 4 + tid; i < n; i += 256) {
        float e = __expf(p[i] - m);
        p[i] = e;
        s += e;
    }
    s = warp_sum(s);
    if (lane == 0) red[wid] = s;
    __syncthreads();
    if (wid == 0) {
        float x = (lane < 8) ? red[lane] : 0.f;
        x = warp_sum(x);
        if (lane == 0) red[0] = x;
    }
    __syncthreads();
    float inv = 1.f / red[0];

    for (int i = tid; i < n4; i += 256) {
        float4 v = p4[i];
        v.x = tf32r(v.x * inv); v.y = tf32r(v.y * inv);
        v.z = tf32r(v.z * inv); v.w = tf32r(v.w * inv);
        p4[i] = v;
    }
    for (int i = n4 * 4 + tid; i < n; i += 256) p[i] = tf32r(p[i] * inv);

    int zend = min(T, ((t >> 7) + 1) << 7);
    for (int i = n + tid; i < zend; i += 256) p[i] = 0.f;
}

// ---------------------------------------------------------------------------
extern "C" void kernel_launch(void* const* d_in, const int* in_sizes, int n_in,
                              void* d_out, int out_size)
{
    const float* x  = (const float*)d_in[0];   // [B,T,C]
    const float* Wk = (const float*)d_in[1];   // [H,C]
    const float* Wq = (const float*)d_in[2];   // [H,C]
    const float* Wv = (const float*)d_in[3];   // [H,C]
    float* out = (float*)d_out;                // [B,T,H]

    float* q;  cudaGetSymbolAddress((void**)&q,  g_q);
    float* k;  cudaGetSymbolAddress((void**)&k,  g_k);
    float* vt; cudaGetSymbolAddress((void**)&vt, g_v);
    float* s;  cudaGetSymbolAddress((void**)&s,  g_s);
    float* xr; cudaGetSymbolAddress((void**)&xr, g_xr);
    float* wr; cudaGetSymbolAddress((void**)&wr, g_wr);

    cudaFuncSetAttribute(mma_nt, cudaFuncAttributeMaxDynamicSharedMemorySize,
                         SMEM_BYTES);

    const int M = BB * TT;                 // 8192
    const int HC = HH * CC;                // 2M
    const float scale = rsqrtf((float)HH);

    // 0) pre-round operands to tf32 (RNA: unbiased)
    int nx = BB * TT * CC;
    round_pass<<<(nx / 4 + 255) / 256, 256>>>(x, xr, nx);
    round_pass<<<(HC / 4 + 255) / 256, 256>>>(Wk, wr,          HC);
    round_pass<<<(HC / 4 + 255) / 256, 256>>>(Wq, wr + HC,     HC);
    round_pass<<<(HC / 4 + 255) / 256, 256>>>(Wv, wr + 2 * HC, HC);

    // 1) Q,K projections: [M,C] x [H,C]^T -> [M,H]  (outputs tf32-rounded)
    dim3 gp(HH / BN, M / BM, 1);
    mma_nt<<<gp, 256, SMEM_BYTES>>>(xr, wr + HC, q, M, HH, CC, 1.f,
                                    0, 0, 1, 0, 0, 0);
    mma_nt<<<gp, 256, SMEM_BYTES>>>(xr, wr,      k, M, HH, CC, 1.f,
                                    0, 0, 1, 0, 0, 0);

    // 1b) Vt = Wv * x_b^T -> [H,T] per batch (transposed V, coalesced)
    dim3 gv(TT / BN, HH / BM, BB);
    mma_nt<<<gv, 256, SMEM_BYTES>>>(wr + 2 * HC, xr, vt, HH, TT, CC, 1.f,
                                    0, 0, 1,
                                    0, (long long)TT * CC, (long long)HH * TT);

    // 2) S_b = scale * Q_b K_b^T  (causal tile skip at 2*bx > by)
    dim3 gs(TT / BN, TT / BM, BB);
    mma_nt<<<gs, 256, SMEM_BYTES>>>(q, k, s, TT, TT, HH, scale, 1, 0, 0,
                                    (long long)TT * HH, (long long)TT * HH,
                                    (long long)TT * TT);

    // 3) softmax (rounds P) + zero diag-block tail
    softmax_causal<<<BB * TT, 256>>>(s, TT);

    // 4) O_b = P_b Vt_b^T  (k-limit per block row)
    dim3 go(HH / BN, TT / BM, BB);
    mma_nt<<<go, 256, SMEM_BYTES>>>(s, vt, out, TT, HH, TT, 1.f, 0, 1, 0,
                                    (long long)TT * TT, (long long)HH * TT,
                                    (long long)TT * HH);
}

// round 16
// speedup vs baseline: 1.1377x; 1.1377x over previous
#include <cuda_runtime.h>
#include <cstdint>
#include <math.h>

#define BB 4
#define TT 2048
#define CC 1024
#define HH 2048

// ---- scratch (device globals; allocation-free rule) -----------------------
__device__ float g_q[(size_t)BB * TT * HH];
__device__ float g_k[(size_t)BB * TT * HH];
__device__ float g_v[(size_t)BB * TT * HH];      // V TRANSPOSED: [B][H][T]
__device__ float g_s[(size_t)BB * TT * TT];
__device__ float g_xr[(size_t)BB * TT * CC];     // tf32-rounded x
__device__ float g_wr[(size_t)3 * HH * CC];      // tf32-rounded Wk|Wq|Wv

// ---- helpers --------------------------------------------------------------
__device__ __forceinline__ uint32_t smem_u32(const void* p) {
    uint32_t a;
    asm("{ .reg .u64 t; cvta.to.shared.u64 t, %1; cvt.u32.u64 %0, t; }"
        : "=r"(a) : "l"(p));
    return a;
}
__device__ __forceinline__ float tf32r(float v) {
    uint32_t u;
    asm("cvt.rna.tf32.f32 %0, %1;" : "=r"(u) : "f"(v));
    return __uint_as_float(u);
}

#define CP16(dst, src) \
    asm volatile("cp.async.cg.shared.global [%0], [%1], 16;" \
                 :: "r"(dst), "l"(src))
#define CP_COMMIT() asm volatile("cp.async.commit_group;" ::: "memory")
#define CP_WAIT0()  asm volatile("cp.async.wait_group 0;" ::: "memory")

#define LDSM4(r0, r1, r2, r3, a) \
    asm volatile("ldmatrix.sync.aligned.m8n8.x4.shared.b16 {%0,%1,%2,%3}, [%4];" \
                 : "=r"(r0), "=r"(r1), "=r"(r2), "=r"(r3) : "r"(a))

#define MMA8(d, a, b0, b1) \
    asm volatile("mma.sync.aligned.m16n8k8.row.col.f32.tf32.tf32.f32 " \
        "{%0,%1,%2,%3}, {%4,%5,%6,%7}, {%8,%9}, {%0,%1,%2,%3};" \
        : "+f"((d)[0]), "+f"((d)[1]), "+f"((d)[2]), "+f"((d)[3]) \
        : "r"((a)[0]), "r"((a)[1]), "r"((a)[2]), "r"((a)[3]), \
          "r"(b0), "r"(b1))

// ---- GEMM config (round-14 winner: 128x128x32, 2 CTAs/SM) -----------------
#define BM 128
#define BN 128
#define BK 32
#define PADK 36                         // floats per smem row (144B; 9x16B units)
#define TBUF (BM * PADK)                // floats per buffer (4608)
#define TBUF_B (TBUF * 4)               // 18432 bytes
#define SMEM_BYTES (4 * TBUF_B)         // A[2] + B[2] = 73728

// ---------------------------------------------------------------------------
// C[M,N] = scale * A[M,K] * B[N,K]^T  (row-major, K contiguous)
// tf32 mma.sync m16n8k8, 128x128x32 tiles, 8 warps (2x4), warp tile 64x32,
// cp.async double buffer with ONE barrier per K-tile:
//   wait(t) -> sync -> prefetch(t+1) -> compute(t)
// causal: skip tiles bx > by.  klimit: K bounded at (by+1)*BM.
// round_out: RNA-round outputs to tf32 (tensors feeding another MMA).
// ---------------------------------------------------------------------------
__global__ __launch_bounds__(256, 2)
void mma_nt(const float* __restrict__ A, const float* __restrict__ B,
            float* __restrict__ C, int M, int N, int K, float scale,
            int causal, int klimit, int round_out,
            long long sA, long long sB, long long sC)
{
    int bx = blockIdx.x, by = blockIdx.y, bz = blockIdx.z;
    if (causal && bx > by) return;
    A += (long long)bz * sA;
    B += (long long)bz * sB;
    C += (long long)bz * sC;

    extern __shared__ float dsm[];
    float* As = dsm;                    // [2][TBUF]
    float* Bs = dsm + 2 * TBUF;         // [2][TBUF]

    int tid = threadIdx.x;
    int lane = tid & 31, wid = tid >> 5;
    int warp_m = wid >> 2;              // 0..1 -> 64-row half
    int warp_n = wid & 3;               // 0..3 -> 32-col quarter

    const float* Ab = A + (size_t)(by * BM) * K;
    const float* Bb = B + (size_t)(bx * BN) * K;

    int kend = klimit ? min(K, (by + 1) * BM) : K;
    int nt = kend / BK;

    uint32_t as0 = smem_u32(As);
    uint32_t bs0 = smem_u32(Bs);

    // cp.async: per matrix 128 rows x 8 chunks(16B); 256 thr x 4 chunks.
    int crow = tid >> 3;                // 0..31 (+32*i)
    int ccol = (tid & 7) * 4;           // float offset in row
    uint32_t dA = as0 + (uint32_t)(crow * PADK + ccol) * 4;
    uint32_t dB = bs0 + (uint32_t)(crow * PADK + ccol) * 4;
    const float* sAp = Ab + (size_t)crow * K + ccol;
    const float* sBp = Bb + (size_t)crow * K + ccol;
    const uint32_t rstep = 32 * PADK * 4;   // 32 rows in smem bytes

    // ldmatrix bases
    uint32_t aAddr = as0 + (uint32_t)(((warp_m * 64 + (lane & 15)) * PADK
                                       + (lane >> 4) * 4) * 4);
    uint32_t bAddr = bs0 + (uint32_t)(((warp_n * 32 + (lane & 7)
                                        + ((lane >> 4) & 1) * 8) * PADK
                                       + ((lane >> 3) & 1) * 4) * 4);

    float acc[4][4][4];
#pragma unroll
    for (int i = 0; i < 4; i++)
#pragma unroll
        for (int j = 0; j < 4; j++)
#pragma unroll
            for (int r = 0; r < 4; r++) acc[i][j][r] = 0.f;

    // preload tile 0
#pragma unroll
    for (int i = 0; i < 4; i++) {
        CP16(dA + i * rstep, sAp + (size_t)(i * 32) * K);
        CP16(dB + i * rstep, sBp + (size_t)(i * 32) * K);
    }
    CP_COMMIT();

    for (int t = 0; t < nt; t++) {
        uint32_t boff = (uint32_t)(t & 1) * TBUF_B;

        // tile t ready (only tile t's group is outstanding here)
        CP_WAIT0();
        __syncthreads();   // data visible + prev readers of other buffer done

        // prefetch t+1 into the other buffer; overlaps compute below
        if (t + 1 < nt) {
            uint32_t nboff = (uint32_t)((t + 1) & 1) * TBUF_B;
            size_t ko = (size_t)(t + 1) * BK;
#pragma unroll
            for (int i = 0; i < 4; i++) {
                CP16(dA + nboff + i * rstep, sAp + (size_t)(i * 32) * K + ko);
                CP16(dB + nboff + i * rstep, sBp + (size_t)(i * 32) * K + ko);
            }
            CP_COMMIT();
        }

#pragma unroll
        for (int ks = 0; ks < 4; ks++) {
            uint32_t a[4][4], b[2][4];
#pragma unroll
            for (int mi = 0; mi < 4; mi++)
                LDSM4(a[mi][0], a[mi][1], a[mi][2], a[mi][3],
                      aAddr + boff + (uint32_t)(mi * 16 * PADK * 4 + ks * 32));
#pragma unroll
            for (int g = 0; g < 2; g++)
                LDSM4(b[g][0], b[g][1], b[g][2], b[g][3],
                      bAddr + boff + (uint32_t)(g * 16 * PADK * 4 + ks * 32));
#pragma unroll
            for (int mi = 0; mi < 4; mi++)
#pragma unroll
                for (int g = 0; g < 2; g++) {
                    MMA8(acc[mi][2 * g],     a[mi], b[g][0], b[g][1]);
                    MMA8(acc[mi][2 * g + 1], a[mi], b[g][2], b[g][3]);
                }
        }
    }

    // epilogue
#pragma unroll
    for (int mi = 0; mi < 4; mi++) {
#pragma unroll
        for (int ni = 0; ni < 4; ni++) {
            int r0 = by * BM + warp_m * 64 + mi * 16 + (lane >> 2);
            int c  = bx * BN + warp_n * 32 + ni * 8 + 2 * (lane & 3);
            float2 v0, v1;
            v0.x = acc[mi][ni][0] * scale; v0.y = acc[mi][ni][1] * scale;
            v1.x = acc[mi][ni][2] * scale; v1.y = acc[mi][ni][3] * scale;
            if (round_out) {
                v0.x = tf32r(v0.x); v0.y = tf32r(v0.y);
                v1.x = tf32r(v1.x); v1.y = tf32r(v1.y);
            }
            *(float2*)(C + (size_t)r0 * N + c)       = v0;
            *(float2*)(C + (size_t)(r0 + 8) * N + c) = v1;
        }
    }
}

// ---- tf32 pre-rounding pass ----------------------------------------------
__global__ __launch_bounds__(256)
void round_pass(const float* __restrict__ in, float* __restrict__ out, int n)
{
    int i = (blockIdx.x * 256 + threadIdx.x) * 4;
    if (i < n) {
        float4 v = *(const float4*)(in + i);
        v.x = tf32r(v.x); v.y = tf32r(v.y); v.z = tf32r(v.z); v.w = tf32r(v.w);
        *(float4*)(out + i) = v;
    }
}

// ---- causal softmax (in-place, float4), rounds P to tf32, zero diag tail --
__device__ __forceinline__ float warp_max(float v) {
#pragma unroll
    for (int o = 16; o; o >>= 1) v = fmaxf(v, __shfl_xor_sync(0xffffffffu, v, o));
    return v;
}
__device__ __forceinline__ float warp_sum(float v) {
#pragma unroll
    for (int o = 16; o; o >>= 1) v += __shfl_xor_sync(0xffffffffu, v, o);
    return v;
}

__global__ __launch_bounds__(256)
void softmax_causal(float* __restrict__ S, int T)
{
    int row = blockIdx.x;
    int b = row / T;
    int t = row - b * T;
    float* p = S + (long long)b * T * T + (long long)t * T;
    float4* p4 = (float4*)p;
    int n = t + 1;
    int n4 = n >> 2;

    int tid = threadIdx.x;
    int lane = tid & 31, wid = tid >> 5;
    __shared__ float red[8];

    float m = -INFINITY;
    for (int i = tid; i < n4; i += 256) {
        float4 v = p4[i];
        m = fmaxf(m, fmaxf(fmaxf(v.x, v.y), fmaxf(v.z, v.w)));
    }
    for (int i = n4 * 4 + tid; i < n; i += 256) m = fmaxf(m, p[i]);
    m = warp_max(m);
    if (lane == 0) red[wid] = m;
    __syncthreads();
    if (wid == 0) {
        float x = (lane < 8) ? red[lane] : -INFINITY;
        x = warp_max(x);
        if (lane == 0) red[0] = x;
    }
    __syncthreads();
    m = red[0];
    __syncthreads();

    float s = 0.f;
    for (int i = tid; i < n4; i += 256) {
        float4 v = p4[i];
        v.x = __expf(v.x - m); v.y = __expf(v.y - m);
        v.z = __expf(v.z - m); v.w = __expf(v.w - m);
        s += v.x + v.y + v.z + v.w;
        p4[i] = v;
    }
    for (int i = n4 * 4 + tid; i < n; i += 256) {
        float e = __expf(p[i] - m);
        p[i] = e;
        s += e;
    }
    s = warp_sum(s);
    if (lane == 0) red[wid] = s;
    __syncthreads();
    if (wid == 0) {
        float x = (lane < 8) ? red[lane] : 0.f;
        x = warp_sum(x);
        if (lane == 0) red[0] = x;
    }
    __syncthreads();
    float inv = 1.f / red[0];

    for (int i = tid; i < n4; i += 256) {
        float4 v = p4[i];
        v.x = tf32r(v.x * inv); v.y = tf32r(v.y * inv);
        v.z = tf32r(v.z * inv); v.w = tf32r(v.w * inv);
        p4[i] = v;
    }
    for (int i = n4 * 4 + tid; i < n; i += 256) p[i] = tf32r(p[i] * inv);

    int zend = min(T, ((t >> 7) + 1) << 7);
    for (int i = n + tid; i < zend; i += 256) p[i] = 0.f;
}

// ---------------------------------------------------------------------------
extern "C" void kernel_launch(void* const* d_in, const int* in_sizes, int n_in,
                              void* d_out, int out_size)
{
    const float* x  = (const float*)d_in[0];   // [B,T,C]
    const float* Wk = (const float*)d_in[1];   // [H,C]
    const float* Wq = (const float*)d_in[2];   // [H,C]
    const float* Wv = (const float*)d_in[3];   // [H,C]
    float* out = (float*)d_out;                // [B,T,H]

    float* q;  cudaGetSymbolAddress((void**)&q,  g_q);
    float* k;  cudaGetSymbolAddress((void**)&k,  g_k);
    float* vt; cudaGetSymbolAddress((void**)&vt, g_v);
    float* s;  cudaGetSymbolAddress((void**)&s,  g_s);
    float* xr; cudaGetSymbolAddress((void**)&xr, g_xr);
    float* wr; cudaGetSymbolAddress((void**)&wr, g_wr);

    cudaFuncSetAttribute(mma_nt, cudaFuncAttributeMaxDynamicSharedMemorySize,
                         SMEM_BYTES);

    const int M = BB * TT;                 // 8192
    const int HC = HH * CC;                // 2M
    const float scale = rsqrtf((float)HH);

    // 0) pre-round operands to tf32 (RNA: unbiased)
    int nx = BB * TT * CC;
    round_pass<<<(nx / 4 + 255) / 256, 256>>>(x, xr, nx);
    round_pass<<<(HC / 4 + 255) / 256, 256>>>(Wk, wr,          HC);
    round_pass<<<(HC / 4 + 255) / 256, 256>>>(Wq, wr + HC,     HC);
    round_pass<<<(HC / 4 + 255) / 256, 256>>>(Wv, wr + 2 * HC, HC);

    // 1) Q,K projections: [M,C] x [H,C]^T -> [M,H]  (outputs tf32-rounded)
    dim3 gp(HH / BN, M / BM, 1);
    mma_nt<<<gp, 256, SMEM_BYTES>>>(xr, wr + HC, q, M, HH, CC, 1.f,
                                    0, 0, 1, 0, 0, 0);
    mma_nt<<<gp, 256, SMEM_BYTES>>>(xr, wr,      k, M, HH, CC, 1.f,
                                    0, 0, 1, 0, 0, 0);

    // 1b) Vt = Wv * x_b^T -> [H,T] per batch (transposed V, coalesced)
    dim3 gv(TT / BN, HH / BM, BB);
    mma_nt<<<gv, 256, SMEM_BYTES>>>(wr + 2 * HC, xr, vt, HH, TT, CC, 1.f,
                                    0, 0, 1,
                                    0, (long long)TT * CC, (long long)HH * TT);

    // 2) S_b = scale * Q_b K_b^T  (causal tile skip)
    dim3 gs(TT / BN, TT / BM, BB);
    mma_nt<<<gs, 256, SMEM_BYTES>>>(q, k, s, TT, TT, HH, scale, 1, 0, 0,
                                    (long long)TT * HH, (long long)TT * HH,
                                    (long long)TT * TT);

    // 3) softmax (rounds P) + zero diag-block tail
    softmax_causal<<<BB * TT, 256>>>(s, TT);

    // 4) O_b = P_b Vt_b^T  (k-limit per block row)
    dim3 go(HH / BN, TT / BM, BB);
    mma_nt<<<go, 256, SMEM_BYTES>>>(s, vt, out, TT, HH, TT, 1.f, 0, 1, 0,
                                    (long long)TT * TT, (long long)HH * TT,
                                    (long long)TT * HH);
}

// round 17
// speedup vs baseline: 2.1565x; 1.8955x over previous
#include <cuda_runtime.h>
#include <cuda_fp16.h>
#include <cstdint>
#include <math.h>

#define BB 4
#define TT 2048
#define CC 1024
#define HH 2048

// ---- scratch (device globals; allocation-free rule) -----------------------
__device__ __half g_q[(size_t)BB * TT * HH];
__device__ __half g_k[(size_t)BB * TT * HH];
__device__ __half g_v[(size_t)BB * TT * HH];     // V TRANSPOSED: [B][H][T]
__device__ float  g_s[(size_t)BB * TT * TT];     // fp32 scores
__device__ __half g_p[(size_t)BB * TT * TT];     // fp16 probabilities
__device__ __half g_xh[(size_t)BB * TT * CC];    // fp16 x
__device__ __half g_wh[(size_t)3 * HH * CC];     // fp16 Wk|Wq|Wv

// ---- helpers --------------------------------------------------------------
__device__ __forceinline__ uint32_t smem_u32(const void* p) {
    uint32_t a;
    asm("{ .reg .u64 t; cvta.to.shared.u64 t, %1; cvt.u32.u64 %0, t; }"
        : "=r"(a) : "l"(p));
    return a;
}

#define CP16(dst, src) \
    asm volatile("cp.async.cg.shared.global [%0], [%1], 16;" \
                 :: "r"(dst), "l"(src))
#define CP_COMMIT() asm volatile("cp.async.commit_group;" ::: "memory")
#define CP_WAIT1()  asm volatile("cp.async.wait_group 1;" ::: "memory")
#define CP_WAIT0()  asm volatile("cp.async.wait_group 0;" ::: "memory")

#define LDSM4(r0, r1, r2, r3, a) \
    asm volatile("ldmatrix.sync.aligned.m8n8.x4.shared.b16 {%0,%1,%2,%3}, [%4];" \
                 : "=r"(r0), "=r"(r1), "=r"(r2), "=r"(r3) : "r"(a))

#define MMAH(d, a, b0, b1) \
    asm volatile("mma.sync.aligned.m16n8k16.row.col.f32.f16.f16.f32 " \
        "{%0,%1,%2,%3}, {%4,%5,%6,%7}, {%8,%9}, {%0,%1,%2,%3};" \
        : "+f"((d)[0]), "+f"((d)[1]), "+f"((d)[2]), "+f"((d)[3]) \
        : "r"((a)[0]), "r"((a)[1]), "r"((a)[2]), "r"((a)[3]), \
          "r"(b0), "r"(b1))

// ---- GEMM config ----------------------------------------------------------
#define BM 128
#define BN 128
#define BK 64                            // halves per K-tile (128B row)
#define PADK 72                          // halves per smem row (144B; 9x16B)
#define TBUF (BM * PADK)                 // halves per buffer (9216)
#define TBUF_B (TBUF * 2)                // 18432 bytes
#define SMEM_BYTES (4 * TBUF_B)          // A[2] + B[2] = 73728

// ---------------------------------------------------------------------------
// C[M,N] = scale * A[M,K] * B[N,K]^T  (fp16 operands, K contiguous)
// fp16 mma.sync m16n8k16, 128x128x64 tiles, 8 warps (2x4), warp tile 64x32,
// cp.async double buffer (round-14 structure: prefetch -> wait1 -> sync).
// causal: skip tiles bx > by.  klimit: K bounded at (by+1)*BM.
// out_half: write C as fp16 (__half2 stores); else fp32 (float2 stores).
// ---------------------------------------------------------------------------
__global__ __launch_bounds__(256, 2)
void mma_nt_f16(const __half* __restrict__ A, const __half* __restrict__ B,
                void* __restrict__ Cv, int M, int N, int K, float scale,
                int causal, int klimit, int out_half,
                long long sA, long long sB, long long sC)
{
    int bx = blockIdx.x, by = blockIdx.y, bz = blockIdx.z;
    if (causal && bx > by) return;
    A += (long long)bz * sA;
    B += (long long)bz * sB;

    extern __shared__ __half hsm[];
    __half* As = hsm;                    // [2][TBUF]
    __half* Bs = hsm + 2 * TBUF;         // [2][TBUF]

    int tid = threadIdx.x;
    int lane = tid & 31, wid = tid >> 5;
    int warp_m = wid >> 2;               // 0..1 -> 64-row half
    int warp_n = wid & 3;                // 0..3 -> 32-col quarter

    const __half* Ab = A + (size_t)(by * BM) * K;
    const __half* Bb = B + (size_t)(bx * BN) * K;

    int kend = klimit ? min(K, (by + 1) * BM) : K;
    int nt = kend / BK;

    uint32_t as0 = smem_u32(As);
    uint32_t bs0 = smem_u32(Bs);

    // cp.async: rows of 64 halves = 8 chunks(16B); 128 rows -> 4 chunks/thr.
    int crow = tid >> 3;                 // 0..31 (+32*i)
    int ccol = (tid & 7) * 8;            // half offset in row (8 halves/chunk)
    uint32_t dA = as0 + (uint32_t)(crow * PADK + ccol) * 2;
    uint32_t dB = bs0 + (uint32_t)(crow * PADK + ccol) * 2;
    const __half* sAp = Ab + (size_t)crow * K + ccol;
    const __half* sBp = Bb + (size_t)crow * K + ccol;
    const uint32_t rstep = 32 * PADK * 2;    // 32 rows in smem bytes

    // ldmatrix bases (b16 elements)
    // A 16x16 frag: lanes 0-15 rows, lanes 16-31 same rows +8 halves (16B)
    uint32_t aAddr = as0 + (uint32_t)(((warp_m * 64 + (lane & 15)) * PADK
                                       + (lane >> 4) * 8) * 2);
    // B: two n8k16 frags per LDSM4: lanes 0-7 n0-7 k0, 8-15 n0-7 k+8,
    //    16-23 n8-15 k0, 24-31 n8-15 k+8
    uint32_t bAddr = bs0 + (uint32_t)(((warp_n * 32 + (lane & 7)
                                        + ((lane >> 4) & 1) * 8) * PADK
                                       + ((lane >> 3) & 1) * 8) * 2);

    float acc[4][4][4];
#pragma unroll
    for (int i = 0; i < 4; i++)
#pragma unroll
        for (int j = 0; j < 4; j++)
#pragma unroll
            for (int r = 0; r < 4; r++) acc[i][j][r] = 0.f;

    // preload tile 0
#pragma unroll
    for (int i = 0; i < 4; i++) {
        CP16(dA + i * rstep, sAp + (size_t)(i * 32) * K);
        CP16(dB + i * rstep, sBp + (size_t)(i * 32) * K);
    }
    CP_COMMIT();

    for (int t = 0; t < nt; t++) {
        uint32_t boff = (uint32_t)(t & 1) * TBUF_B;
        if (t + 1 < nt) {
            uint32_t nboff = (uint32_t)((t + 1) & 1) * TBUF_B;
            size_t ko = (size_t)(t + 1) * BK;
#pragma unroll
            for (int i = 0; i < 4; i++) {
                CP16(dA + nboff + i * rstep, sAp + (size_t)(i * 32) * K + ko);
                CP16(dB + nboff + i * rstep, sBp + (size_t)(i * 32) * K + ko);
            }
            CP_COMMIT();
            CP_WAIT1();
        } else {
            CP_WAIT0();
        }
        __syncthreads();

#pragma unroll
        for (int ks = 0; ks < 4; ks++) {            // 4 x k16 per BK=64
            uint32_t a[4][4], b[2][4];
#pragma unroll
            for (int mi = 0; mi < 4; mi++)
                LDSM4(a[mi][0], a[mi][1], a[mi][2], a[mi][3],
                      aAddr + boff + (uint32_t)(mi * 16 * PADK * 2 + ks * 32));
#pragma unroll
            for (int g = 0; g < 2; g++)
                LDSM4(b[g][0], b[g][1], b[g][2], b[g][3],
                      bAddr + boff + (uint32_t)(g * 16 * PADK * 2 + ks * 32));
#pragma unroll
            for (int mi = 0; mi < 4; mi++)
#pragma unroll
                for (int g = 0; g < 2; g++) {
                    MMAH(acc[mi][2 * g],     a[mi], b[g][0], b[g][1]);
                    MMAH(acc[mi][2 * g + 1], a[mi], b[g][2], b[g][3]);
                }
        }
        __syncthreads();
    }

    // epilogue
#pragma unroll
    for (int mi = 0; mi < 4; mi++) {
#pragma unroll
        for (int ni = 0; ni < 4; ni++) {
            int r0 = by * BM + warp_m * 64 + mi * 16 + (lane >> 2);
            int c  = bx * BN + warp_n * 32 + ni * 8 + 2 * (lane & 3);
            float2 v0, v1;
            v0.x = acc[mi][ni][0] * scale; v0.y = acc[mi][ni][1] * scale;
            v1.x = acc[mi][ni][2] * scale; v1.y = acc[mi][ni][3] * scale;
            if (out_half) {
                __half* Ch = (__half*)Cv + (long long)bz * sC;
                *(__half2*)(Ch + (size_t)r0 * N + c) =
                    __floats2half2_rn(v0.x, v0.y);
                *(__half2*)(Ch + (size_t)(r0 + 8) * N + c) =
                    __floats2half2_rn(v1.x, v1.y);
            } else {
                float* Cf = (float*)Cv + (long long)bz * sC;
                *(float2*)(Cf + (size_t)r0 * N + c)       = v0;
                *(float2*)(Cf + (size_t)(r0 + 8) * N + c) = v1;
            }
        }
    }
}

// ---- fp32 -> fp16 conversion pass ----------------------------------------
__global__ __launch_bounds__(256)
void cvt_pass(const float* __restrict__ in, __half* __restrict__ out, int n)
{
    int i = (blockIdx.x * 256 + threadIdx.x) * 4;
    if (i < n) {
        float4 v = *(const float4*)(in + i);
        __half2 h0 = __floats2half2_rn(v.x, v.y);
        __half2 h1 = __floats2half2_rn(v.z, v.w);
        *(__half2*)(out + i)     = h0;
        *(__half2*)(out + i + 2) = h1;
    }
}

// ---- causal softmax: fp32 S in, fp16 P out, zero diag-block tail ----------
__device__ __forceinline__ float warp_max(float v) {
#pragma unroll
    for (int o = 16; o; o >>= 1) v = fmaxf(v, __shfl_xor_sync(0xffffffffu, v, o));
    return v;
}
__device__ __forceinline__ float warp_sum(float v) {
#pragma unroll
    for (int o = 16; o; o >>= 1) v += __shfl_xor_sync(0xffffffffu, v, o);
    return v;
}

__global__ __launch_bounds__(256)
void softmax_causal(const float* __restrict__ S, __half* __restrict__ P, int T)
{
    int row = blockIdx.x;
    int b = row / T;
    int t = row - b * T;
    const float* p = S + (long long)b * T * T + (long long)t * T;
    __half* ph = P + (long long)b * T * T + (long long)t * T;
    const float4* p4 = (const float4*)p;
    int n = t + 1;
    int n4 = n >> 2;

    int tid = threadIdx.x;
    int lane = tid & 31, wid = tid >> 5;
    __shared__ float red[8];

    float m = -INFINITY;
    for (int i = tid; i < n4; i += 256) {
        float4 v = p4[i];
        m = fmaxf(m, fmaxf(fmaxf(v.x, v.y), fmaxf(v.z, v.w)));
    }
    for (int i = n4 * 4 + tid; i < n; i += 256) m = fmaxf(m, p[i]);
    m = warp_max(m);
    if (lane == 0) red[wid] = m;
    __syncthreads();
    if (wid == 0) {
        float x = (lane < 8) ? red[lane] : -INFINITY;
        x = warp_max(x);
        if (lane == 0) red[0] = x;
    }
    __syncthreads();
    m = red[0];
    __syncthreads();

    float s = 0.f;
    for (int i = tid; i < n4; i += 256) {
        float4 v = p4[i];
        s += __expf(v.x - m) + __expf(v.y - m)
           + __expf(v.z - m) + __expf(v.w - m);
    }
    for (int i = n4 * 4 + tid; i < n; i += 256) s += __expf(p[i] - m);
    s = warp_sum(s);
    if (lane == 0) red[wid] = s;
    __syncthreads();
    if (wid == 0) {
        float x = (lane < 8) ? red[lane] : 0.f;
        x = warp_sum(x);
        if (lane == 0) red[0] = x;
    }
    __syncthreads();
    float inv = 1.f / red[0];

    // write normalized probabilities as fp16
    for (int i = tid; i < n4; i += 256) {
        float4 v = p4[i];
        __half2 h0 = __floats2half2_rn(__expf(v.x - m) * inv,
                                       __expf(v.y - m) * inv);
        __half2 h1 = __floats2half2_rn(__expf(v.z - m) * inv,
                                       __expf(v.w - m) * inv);
        *(__half2*)(ph + i * 4)     = h0;
        *(__half2*)(ph + i * 4 + 2) = h1;
    }
    for (int i = n4 * 4 + tid; i < n; i += 256)
        ph[i] = __float2half_rn(__expf(p[i] - m) * inv);

    int zend = min(T, ((t >> 7) + 1) << 7);
    for (int i = n + tid; i < zend; i += 256) ph[i] = __float2half_rn(0.f);
}

// ---------------------------------------------------------------------------
extern "C" void kernel_launch(void* const* d_in, const int* in_sizes, int n_in,
                              void* d_out, int out_size)
{
    const float* x  = (const float*)d_in[0];   // [B,T,C]
    const float* Wk = (const float*)d_in[1];   // [H,C]
    const float* Wq = (const float*)d_in[2];   // [H,C]
    const float* Wv = (const float*)d_in[3];   // [H,C]
    float* out = (float*)d_out;                // [B,T,H]

    __half* q;  cudaGetSymbolAddress((void**)&q,  g_q);
    __half* k;  cudaGetSymbolAddress((void**)&k,  g_k);
    __half* vt; cudaGetSymbolAddress((void**)&vt, g_v);
    float*  s;  cudaGetSymbolAddress((void**)&s,  g_s);
    __half* p;  cudaGetSymbolAddress((void**)&p,  g_p);
    __half* xh; cudaGetSymbolAddress((void**)&xh, g_xh);
    __half* wh; cudaGetSymbolAddress((void**)&wh, g_wh);

    cudaFuncSetAttribute(mma_nt_f16,
                         cudaFuncAttributeMaxDynamicSharedMemorySize,
                         SMEM_BYTES);

    const int M = BB * TT;                 // 8192
    const int HC = HH * CC;                // 2M
    const float scale = rsqrtf((float)HH);

    // 0) convert operands to fp16
    int nx = BB * TT * CC;
    cvt_pass<<<(nx / 4 + 255) / 256, 256>>>(x, xh, nx);
    cvt_pass<<<(HC / 4 + 255) / 256, 256>>>(Wk, wh,          HC);
    cvt_pass<<<(HC / 4 + 255) / 256, 256>>>(Wq, wh + HC,     HC);
    cvt_pass<<<(HC / 4 + 255) / 256, 256>>>(Wv, wh + 2 * HC, HC);

    // 1) Q,K projections: [M,C] x [H,C]^T -> fp16 [M,H]
    dim3 gp(HH / BN, M / BM, 1);
    mma_nt_f16<<<gp, 256, SMEM_BYTES>>>(xh, wh + HC, q, M, HH, CC, 1.f,
                                        0, 0, 1, 0, 0, 0);
    mma_nt_f16<<<gp, 256, SMEM_BYTES>>>(xh, wh,      k, M, HH, CC, 1.f,
                                        0, 0, 1, 0, 0, 0);

    // 1b) Vt = Wv * x_b^T -> fp16 [H,T] per batch
    dim3 gv(TT / BN, HH / BM, BB);
    mma_nt_f16<<<gv, 256, SMEM_BYTES>>>(wh + 2 * HC, xh, vt, HH, TT, CC, 1.f,
                                        0, 0, 1,
                                        0, (long long)TT * CC,
                                        (long long)HH * TT);

    // 2) S_b = scale * Q_b K_b^T -> fp32  (causal tile skip)
    dim3 gs(TT / BN, TT / BM, BB);
    mma_nt_f16<<<gs, 256, SMEM_BYTES>>>(q, k, s, TT, TT, HH, scale, 1, 0, 0,
                                        (long long)TT * HH,
                                        (long long)TT * HH,
                                        (long long)TT * TT);

    // 3) softmax: fp32 S -> fp16 P (+ zero diag-block tail)
    softmax_causal<<<BB * TT, 256>>>(s, p, TT);

    // 4) O_b = P_b Vt_b^T -> fp32  (k-limit per block row)
    dim3 go(HH / BN, TT / BM, BB);
    mma_nt_f16<<<go, 256, SMEM_BYTES>>>(p, vt, out, TT, HH, TT, 1.f, 0, 1, 0,
                                        (long long)TT * TT,
                                        (long long)HH * TT,
                                        (long long)TT * HH);
}